// round 7
// baseline (speedup 1.0000x reference)
#include <cuda_runtime.h>

// CombPool2d: out = (w_avg^2)*avg_pool2x2(x) + (w_max^2)*max_pool2x2(x)
// x: (16,192,224,224) fp32, out: (16,192,112,112) fp32. Pure HBM stream.
// Thread = 2x2 output block: 4x lane-contiguous float4 loads (MLP_p1=4),
// 2x float2 stores, streaming hints. Flat 1D grid, 256-thread CTAs,
// exact division (37,632 x 256) -> no bounds guard.

#define B   16
#define C   192
#define HI  224
#define WI  224
#define HO  112
#define WO  112
#define H2  (HO / 2)   // output row-pairs = 56
#define WP  (WO / 2)   // output col-pairs = 56

__global__ __launch_bounds__(256)
void comb_pool2d_kernel(const float* __restrict__ x,
                        const float* __restrict__ w_avg,
                        const float* __restrict__ w_max,
                        float* __restrict__ out)
{
    unsigned tid = blockIdx.x * 256u + threadIdx.x;   // exact: no guard needed

    unsigned wp = tid % WP;          // output col-pair (2 output cols)
    unsigned t  = tid / WP;
    unsigned h2 = t % H2;            // output row-pair (2 output rows)
    unsigned bc = t / H2;            // fused batch*channel
    unsigned c  = bc % C;

    // Input: rows 4*h2 .. 4*h2+3, cols 4*wp .. 4*wp+3 (4x4 patch, 16B/row)
    const float* xin = x + (size_t)bc * (HI * WI) + (size_t)(4 * h2) * WI + 4 * wp;

    // Four lane-contiguous 16B loads, front-batched (MLP=4, evict-first)
    float4 r0 = __ldcs(reinterpret_cast<const float4*>(xin));
    float4 r1 = __ldcs(reinterpret_cast<const float4*>(xin + WI));
    float4 r2 = __ldcs(reinterpret_cast<const float4*>(xin + 2 * WI));
    float4 r3 = __ldcs(reinterpret_cast<const float4*>(xin + 3 * WI));

    float wa = __ldg(w_avg + c);
    float wm = __ldg(w_max + c);
    float ca = wa * wa * 0.25f;   // folds the /4 of avg-pool
    float cm = wm * wm;

    float2 o0, o1;
    // rows (r0, r1) -> output row 2*h2
    o0.x = fmaf(ca, (r0.x + r0.y) + (r1.x + r1.y),
                cm * fmaxf(fmaxf(r0.x, r0.y), fmaxf(r1.x, r1.y)));
    o0.y = fmaf(ca, (r0.z + r0.w) + (r1.z + r1.w),
                cm * fmaxf(fmaxf(r0.z, r0.w), fmaxf(r1.z, r1.w)));
    // rows (r2, r3) -> output row 2*h2+1
    o1.x = fmaf(ca, (r2.x + r2.y) + (r3.x + r3.y),
                cm * fmaxf(fmaxf(r2.x, r2.y), fmaxf(r3.x, r3.y)));
    o1.y = fmaf(ca, (r2.z + r2.w) + (r3.z + r3.w),
                cm * fmaxf(fmaxf(r2.z, r2.w), fmaxf(r3.z, r3.w)));

    float* outp = out + (size_t)bc * (HO * WO) + (size_t)(2 * h2) * WO + 2 * wp;
    __stcs(reinterpret_cast<float2*>(outp),      o0);
    __stcs(reinterpret_cast<float2*>(outp + WO), o1);
}

extern "C" void kernel_launch(void* const* d_in, const int* in_sizes, int n_in,
                              void* d_out, int out_size)
{
    const float* x     = (const float*)d_in[0];
    const float* w_avg = (const float*)d_in[1];
    const float* w_max = (const float*)d_in[2];
    float* out = (float*)d_out;

    const int total  = B * C * H2 * WP;          // 9,633,792
    const int blocks = total / 256;              // 37,632 exactly

    comb_pool2d_kernel<<<blocks, 256>>>(x, w_avg, w_max, out);
}

// round 8
// speedup vs baseline: 1.0091x; 1.0091x over previous
#include <cuda_runtime.h>

// CombPool2d: out = (w_avg^2)*avg_pool2x2(x) + (w_max^2)*max_pool2x2(x)
// x: (16,192,224,224) fp32, out: (16,192,112,112) fp32. Pure HBM stream.
// Thread = 2x2 output block: 4x lane-contiguous float4 loads (MLP_p1=4).
// Lane-pair shuffle combines results so each thread issues ONE float4 store
// (even lane -> output row 2h2, odd lane -> row 2h2+1), halving STG count.
// Flat 1D grid, 256-thread CTAs, exact division -> no bounds guard.

#define B   16
#define C   192
#define HI  224
#define WI  224
#define HO  112
#define WO  112
#define H2  (HO / 2)   // output row-pairs = 56
#define WP  (WO / 2)   // output col-pairs = 56 (even -> lane parity == wp parity)

__global__ __launch_bounds__(256)
void comb_pool2d_kernel(const float* __restrict__ x,
                        const float* __restrict__ w_avg,
                        const float* __restrict__ w_max,
                        float* __restrict__ out)
{
    unsigned tid = blockIdx.x * 256u + threadIdx.x;   // exact: no guard

    unsigned wp = tid % WP;          // output col-pair
    unsigned t  = tid / WP;
    unsigned h2 = t % H2;            // output row-pair
    unsigned bc = t / H2;            // fused batch*channel
    unsigned c  = bc % C;

    // Input: rows 4*h2 .. 4*h2+3, cols 4*wp .. 4*wp+3 (4x4 patch, 16B/row)
    const float* xin = x + (size_t)bc * (HI * WI) + (size_t)(4 * h2) * WI + 4 * wp;

    // Four lane-contiguous 16B loads, front-batched (MLP=4, evict-first)
    float4 r0 = __ldcs(reinterpret_cast<const float4*>(xin));
    float4 r1 = __ldcs(reinterpret_cast<const float4*>(xin + WI));
    float4 r2 = __ldcs(reinterpret_cast<const float4*>(xin + 2 * WI));
    float4 r3 = __ldcs(reinterpret_cast<const float4*>(xin + 3 * WI));

    float wa = __ldg(w_avg + c);
    float wm = __ldg(w_max + c);
    float ca = wa * wa * 0.25f;   // folds the /4 of avg-pool
    float cm = wm * wm;

    // o0 = output row 2*h2 (cols 2wp, 2wp+1); o1 = output row 2*h2+1
    float2 o0, o1;
    o0.x = fmaf(ca, (r0.x + r0.y) + (r1.x + r1.y),
                cm * fmaxf(fmaxf(r0.x, r0.y), fmaxf(r1.x, r1.y)));
    o0.y = fmaf(ca, (r0.z + r0.w) + (r1.z + r1.w),
                cm * fmaxf(fmaxf(r0.z, r0.w), fmaxf(r1.z, r1.w)));
    o1.x = fmaf(ca, (r2.x + r2.y) + (r3.x + r3.y),
                cm * fmaxf(fmaxf(r2.x, r2.y), fmaxf(r3.x, r3.y)));
    o1.y = fmaf(ca, (r2.z + r2.w) + (r3.z + r3.w),
                cm * fmaxf(fmaxf(r2.z, r2.w), fmaxf(r3.z, r3.w)));

    // Lane-pair exchange: wp parity == lane parity (WP even, 256 | WP*...).
    // Even lane sends o1 / receives partner's o0 -> owns row 2h2, 4 cols.
    // Odd  lane sends o0 / receives partner's o1 -> owns row 2h2+1, 4 cols.
    unsigned odd = threadIdx.x & 1u;
    float sx = odd ? o0.x : o1.x;
    float sy = odd ? o0.y : o1.y;
    float rx = __shfl_xor_sync(0xFFFFFFFFu, sx, 1);
    float ry = __shfl_xor_sync(0xFFFFFFFFu, sy, 1);

    float4 o;
    if (odd) {            // row 2h2+1: [recv(even's o1) | my o1]
        o.x = rx; o.y = ry; o.z = o1.x; o.w = o1.y;
    } else {              // row 2h2:   [my o0 | recv(odd's o0)]
        o.x = o0.x; o.y = o0.y; o.z = rx; o.w = ry;
    }

    // Store base: col 4*(wp/2), row 2*h2 + parity
    unsigned colb = (wp & ~1u) * 2u;
    float* outp = out + (size_t)bc * (HO * WO)
                      + (size_t)(2 * h2 + odd) * WO + colb;
    __stcs(reinterpret_cast<float4*>(outp), o);
}

extern "C" void kernel_launch(void* const* d_in, const int* in_sizes, int n_in,
                              void* d_out, int out_size)
{
    const float* x     = (const float*)d_in[0];
    const float* w_avg = (const float*)d_in[1];
    const float* w_max = (const float*)d_in[2];
    float* out = (float*)d_out;

    const int total  = B * C * H2 * WP;          // 9,633,792
    const int blocks = total / 256;              // 37,632 exactly

    comb_pool2d_kernel<<<blocks, 256>>>(x, w_avg, w_max, out);
}